// round 1
// baseline (speedup 1.0000x reference)
#include <cuda_runtime.h>
#include <math.h>

// ---------------- problem constants ----------------
#define IMGS 8          // 4 src + 4 tgt
#define CIN  1024
#define P    1024       // 32*32 spatial positions
#define KC   28         // context channels
#define KTOT 1052       // 1024 + 28
#define COUT 2048
#define NB   4          // batch

// ---------------- scratch (device globals; no allocation allowed) ----------------
__device__ float g_inv1[IMGS * P];            // 1/max(||feat||,1e-12)
__device__ float g_ctx [IMGS * KC * P];       // context channels
__device__ float g_S   [IMGS * COUT * P];     // conv output (relu'd), 64MB
__device__ float g_inv2[IMGS * P];            // rsqrt(sumsq + 1e-6)
__device__ float g_corr[NB * P * P];          // corr[b][s][t], 16MB
__device__ float g_smax[NB * P];
__device__ float g_tmax[NB * P];
__device__ float g_corrT[NB * P * P];         // filtered, transposed: [b][t][s]

// offsets (dy,dx) for the 28 context channels (r-3, c-3)
__device__ const int c_dy[28] = {-3,-2,-1,0,1,2,3, -3,-2,-1,0,1,2,3, -3,-2,-1,0,1,2,3, 0,0,0,0,0,0,0};
__device__ const int c_dx[28] = {-3,-2,-1,0,1,2,3,  0, 0, 0,0,0,0,0,  3, 2, 1,0,-1,-2,-3, -3,-2,-1,0,1,2,3};

__device__ __forceinline__ const float* img_ptr(const float* src, const float* tgt, int img) {
    return (img < 4) ? (src + (size_t)img * CIN * P) : (tgt + (size_t)(img - 4) * CIN * P);
}

// ---------------- kernel 1: feature norms -> inv1 ----------------
// grid (8 imgs, 32 rows), 256 thr = 32 x-lanes * 8 channel-groups
__global__ void k_norm1(const float* __restrict__ src, const float* __restrict__ tgt) {
    int img = blockIdx.x, y = blockIdx.y;
    const float* f = img_ptr(src, tgt, img);
    int x = threadIdx.x & 31, cg = threadIdx.x >> 5;
    int p = y * 32 + x;
    float ss = 0.f;
    for (int c = cg; c < CIN; c += 8) { float v = f[c * P + p]; ss = fmaf(v, v, ss); }
    __shared__ float sm[8][32];
    sm[cg][x] = ss;
    __syncthreads();
    if (cg == 0) {
        float s = 0.f;
#pragma unroll
        for (int i = 0; i < 8; i++) s += sm[i][x];
        g_inv1[img * P + p] = 1.f / fmaxf(sqrtf(s), 1e-12f);
    }
}

// ---------------- kernel 2: context channels ----------------
// grid (8 imgs, 32 rows), 256 thr; each warp owns a channel subset (c = w, w+8, ...)
__global__ void k_ctx(const float* __restrict__ src, const float* __restrict__ tgt) {
    int img = blockIdx.x, y = blockIdx.y;
    const float* f = img_ptr(src, tgt, img);
    int lane = threadIdx.x & 31, w = threadIdx.x >> 5;
    __shared__ float tile[8][7][32];
    __shared__ float red[28][8][32];
    float acc[28];
#pragma unroll
    for (int k = 0; k < 28; k++) acc[k] = 0.f;

    for (int c = w; c < CIN; c += 8) {
#pragma unroll
        for (int dy = 0; dy < 7; dy++) {
            int yy = y + dy - 3;
            tile[w][dy][lane] = (yy >= 0 && yy < 32) ? f[c * P + yy * 32 + lane] : 0.f;
        }
        __syncwarp();
        float v0 = tile[w][3][lane];
#pragma unroll
        for (int k = 0; k < 28; k++) {
            int xx = lane + c_dx[k];
            float v = (xx >= 0 && xx < 32) ? tile[w][c_dy[k] + 3][xx] : 0.f;
            acc[k] = fmaf(v0, v, acc[k]);
        }
        __syncwarp();
    }
#pragma unroll
    for (int k = 0; k < 28; k++) red[k][w][lane] = acc[k];
    __syncthreads();

    const float* inv = g_inv1 + img * P;
    for (int idx = threadIdx.x; idx < 28 * 32; idx += 256) {
        int k = idx >> 5, x = idx & 31;
        float s = 0.f;
#pragma unroll
        for (int i = 0; i < 8; i++) s += red[k][i][x];
        int yy = y + c_dy[k], xx = x + c_dx[k];
        float o = 0.f;
        if (yy >= 0 && yy < 32 && xx >= 0 && xx < 32)
            o = s * inv[y * 32 + x] * inv[yy * 32 + xx];
        g_ctx[((size_t)img * KC + k) * P + y * 32 + x] = o;
    }
}

// ---------------- kernel 3: conv GEMM (2048 x 1052) @ (1052 x 1024) + bias + relu ----------------
// classic 128x128x8 SGEMM, A = W row-major, B = [feat; ctx] row-major
__global__ void __launch_bounds__(256, 1)
k_conv(const float* __restrict__ Wt, const float* __restrict__ bias,
       const float* __restrict__ src, const float* __restrict__ tgt) {
    int img = blockIdx.z;
    const float* feat = img_ptr(src, tgt, img);
    const float* ctx  = g_ctx + (size_t)img * KC * P;
    int bm = blockIdx.y * 128, bn = blockIdx.x * 128;
    __shared__ float As[8][128];
    __shared__ float Bs[8][128];
    int tid = threadIdx.x;
    int ty = tid >> 4, tx = tid & 15;
    int arow = tid >> 1, acol = (tid & 1) * 4;
    int brow = tid >> 5, bcol = (tid & 31) * 4;
    float acc[8][8];
#pragma unroll
    for (int i = 0; i < 8; i++)
#pragma unroll
        for (int j = 0; j < 8; j++) acc[i][j] = 0.f;

    for (int k0 = 0; k0 < KTOT; k0 += 8) {
        float4 av = make_float4(0.f, 0.f, 0.f, 0.f);
        if (k0 + acol < KTOT)
            av = *(const float4*)(Wt + (size_t)(bm + arow) * KTOT + k0 + acol);
        As[acol + 0][arow] = av.x; As[acol + 1][arow] = av.y;
        As[acol + 2][arow] = av.z; As[acol + 3][arow] = av.w;

        int kk = k0 + brow;
        float4 bv = make_float4(0.f, 0.f, 0.f, 0.f);
        if (kk < CIN)       bv = *(const float4*)(feat + (size_t)kk * P + bn + bcol);
        else if (kk < KTOT) bv = *(const float4*)(ctx + (size_t)(kk - CIN) * P + bn + bcol);
        *(float4*)&Bs[brow][bcol] = bv;
        __syncthreads();
#pragma unroll
        for (int k2 = 0; k2 < 8; k2++) {
            float a[8], b[8];
#pragma unroll
            for (int i = 0; i < 8; i++) a[i] = As[k2][ty * 8 + i];
#pragma unroll
            for (int j = 0; j < 8; j++) b[j] = Bs[k2][tx * 8 + j];
#pragma unroll
            for (int i = 0; i < 8; i++)
#pragma unroll
                for (int j = 0; j < 8; j++) acc[i][j] = fmaf(a[i], b[j], acc[i][j]);
        }
        __syncthreads();
    }
    float* Sp = g_S + (size_t)img * COUT * P;
#pragma unroll
    for (int i = 0; i < 8; i++) {
        int o = bm + ty * 8 + i;
        float bb = bias[o];
#pragma unroll
        for (int j = 0; j < 8; j++) {
            float v = acc[i][j] + bb;
            Sp[(size_t)o * P + bn + tx * 8 + j] = fmaxf(v, 0.f);
        }
    }
}

// ---------------- kernel 4: l2norm of conv output -> inv2 ----------------
__global__ void k_norm2() {
    int img = blockIdx.x, y = blockIdx.y;
    const float* Sp = g_S + (size_t)img * COUT * P;
    int x = threadIdx.x & 31, cg = threadIdx.x >> 5;
    int p = y * 32 + x;
    float ss = 0.f;
    for (int c = cg; c < COUT; c += 8) { float v = Sp[(size_t)c * P + p]; ss = fmaf(v, v, ss); }
    __shared__ float sm[8][32];
    sm[cg][x] = ss;
    __syncthreads();
    if (cg == 0) {
        float s = 0.f;
#pragma unroll
        for (int i = 0; i < 8; i++) s += sm[i][x];
        g_inv2[img * P + p] = rsqrtf(s + 1e-6f);
    }
}

// ---------------- kernel 5: corr GEMM: corr[b][s][t] = invS[s]*invT[t]*sum_c S[c][s]T[c][t] ----------------
__global__ void __launch_bounds__(256, 1) k_corr() {
    int b = blockIdx.z;
    const float* A = g_S + (size_t)b * COUT * P;          // src
    const float* B = g_S + (size_t)(4 + b) * COUT * P;    // tgt
    int bm = blockIdx.y * 128, bn = blockIdx.x * 128;
    __shared__ float As[8][128], Bs[8][128];
    int tid = threadIdx.x, ty = tid >> 4, tx = tid & 15;
    int lrow = tid >> 5, lcol = (tid & 31) * 4;
    float acc[8][8];
#pragma unroll
    for (int i = 0; i < 8; i++)
#pragma unroll
        for (int j = 0; j < 8; j++) acc[i][j] = 0.f;

    for (int k0 = 0; k0 < COUT; k0 += 8) {
        *(float4*)&As[lrow][lcol] = *(const float4*)(A + (size_t)(k0 + lrow) * P + bm + lcol);
        *(float4*)&Bs[lrow][lcol] = *(const float4*)(B + (size_t)(k0 + lrow) * P + bn + lcol);
        __syncthreads();
#pragma unroll
        for (int k2 = 0; k2 < 8; k2++) {
            float a[8], bb[8];
#pragma unroll
            for (int i = 0; i < 8; i++) a[i] = As[k2][ty * 8 + i];
#pragma unroll
            for (int j = 0; j < 8; j++) bb[j] = Bs[k2][tx * 8 + j];
#pragma unroll
            for (int i = 0; i < 8; i++)
#pragma unroll
                for (int j = 0; j < 8; j++) acc[i][j] = fmaf(a[i], bb[j], acc[i][j]);
        }
        __syncthreads();
    }
    const float* invs = g_inv2 + b * P;
    const float* invt = g_inv2 + (4 + b) * P;
#pragma unroll
    for (int i = 0; i < 8; i++) {
        int s = bm + ty * 8 + i;
        float is = invs[s];
#pragma unroll
        for (int j = 0; j < 8; j++) {
            int t = bn + tx * 8 + j;
            g_corr[((size_t)b * P + s) * P + t] = acc[i][j] * is * invt[t];
        }
    }
}

// ---------------- kernel 6/7: row/col maxes ----------------
__global__ void k_smax() {   // max over t (contiguous rows); warp per s
    int b = blockIdx.x;
    int s = blockIdx.y * 8 + (threadIdx.x >> 5);
    int lane = threadIdx.x & 31;
    const float* row = g_corr + ((size_t)b * P + s) * P;
    float m = -INFINITY;
    for (int t = lane; t < P; t += 32) m = fmaxf(m, row[t]);
#pragma unroll
    for (int o = 16; o > 0; o >>= 1) m = fmaxf(m, __shfl_xor_sync(0xffffffffu, m, o));
    if (lane == 0) g_smax[b * P + s] = m;
}

__global__ void k_tmax() {   // max over s (columns); coalesced across t
    int b = blockIdx.x;
    int t = blockIdx.y * 256 + threadIdx.x;
    const float* c = g_corr + (size_t)b * P * P;
    float m = -INFINITY;
    for (int s = 0; s < P; s++) m = fmaxf(m, c[(size_t)s * P + t]);
    g_tmax[b * P + t] = m;
}

// ---------------- kernel 8: mutual-NN filter + transpose (t-major out) ----------------
__global__ void k_filt() {
    int b = blockIdx.z, s0 = blockIdx.y * 32, t0 = blockIdx.x * 32;
    __shared__ float tile[32][33];
    int lane = threadIdx.x & 31, wy = threadIdx.x >> 5;
    const float* c = g_corr + (size_t)b * P * P;
    for (int r = wy; r < 32; r += 8) {
        int s = s0 + r, t = t0 + lane;
        float v = c[(size_t)s * P + t];
        float sm = g_smax[b * P + s]; sm = (sm == 0.f) ? 1e-30f : sm;
        float tm = g_tmax[b * P + t]; tm = (tm == 0.f) ? 1e-30f : tm;
        tile[r][lane] = v * (v / sm) * (v / tm);
    }
    __syncthreads();
    float* ct = g_corrT + (size_t)b * P * P;
    for (int r = wy; r < 32; r += 8) {
        int t = t0 + r, s = s0 + lane;
        ct[(size_t)t * P + s] = tile[lane][r];
    }
}

// ---------------- kernel 9: fused resize + softmax + soft-argmax + flow ----------------
// one block per output pixel (b, ty, tx); 256 threads
__global__ void __launch_bounds__(256) k_flow(float* __restrict__ out) {
    int tx = blockIdx.x, ty = blockIdx.y, b = blockIdx.z;
    int tid = threadIdx.x;
    const float sc = 31.f / 63.f;

    float fy = ty * sc; int y0 = (int)fy; int y1 = min(y0 + 1, 31); float wy = fy - (float)y0;
    float fx = tx * sc; int x0 = (int)fx; int x1 = min(x0 + 1, 31); float wx = fx - (float)x0;

    const float* C = g_corrT + (size_t)b * P * P;
    const float* r00 = C + (size_t)(y0 * 32 + x0) * P;
    const float* r01 = C + (size_t)(y0 * 32 + x1) * P;
    const float* r10 = C + (size_t)(y1 * 32 + x0) * P;
    const float* r11 = C + (size_t)(y1 * 32 + x1) * P;
    float w00 = (1.f - wy) * (1.f - wx), w01 = (1.f - wy) * wx;
    float w10 = wy * (1.f - wx),         w11 = wy * wx;

    __shared__ float m[P];
    for (int s = tid; s < P; s += 256)
        m[s] = w00 * r00[s] + w01 * r01[s] + w10 * r10[s] + w11 * r11[s];
    __syncthreads();

    // softmax shift: max(m) >= any bilinear combination of m (convex weights)
    float mx = -INFINITY;
    for (int s = tid; s < P; s += 256) mx = fmaxf(mx, m[s]);
    __shared__ float rd[8];
#pragma unroll
    for (int o = 16; o > 0; o >>= 1) mx = fmaxf(mx, __shfl_xor_sync(0xffffffffu, mx, o));
    if ((tid & 31) == 0) rd[tid >> 5] = mx;
    __syncthreads();
    float M = -INFINITY;
#pragma unroll
    for (int i = 0; i < 8; i++) M = fmaxf(M, rd[i]);

    float sum = 0.f, sx = 0.f, sy = 0.f;
    for (int s = tid; s < 4096; s += 256) {
        int i = s >> 6, j = s & 63;
        float gy = i * sc; int yy0 = (int)gy; int yy1 = min(yy0 + 1, 31); float a = gy - (float)yy0;
        float gx = j * sc; int xx0 = (int)gx; int xx1 = min(xx0 + 1, 31); float bq = gx - (float)xx0;
        float v = (1.f - a) * ((1.f - bq) * m[yy0 * 32 + xx0] + bq * m[yy0 * 32 + xx1])
                +        a  * ((1.f - bq) * m[yy1 * 32 + xx0] + bq * m[yy1 * 32 + xx1]);
        float e = expf((v - M) * 50.f);
        sum += e;
        sx = fmaf(e, -1.f + j * (2.f / 63.f), sx);
        sy = fmaf(e, -1.f + i * (2.f / 63.f), sy);
    }
    __shared__ float rs[8], rx[8], ry[8];
#pragma unroll
    for (int o = 16; o > 0; o >>= 1) {
        sum += __shfl_xor_sync(0xffffffffu, sum, o);
        sx  += __shfl_xor_sync(0xffffffffu, sx,  o);
        sy  += __shfl_xor_sync(0xffffffffu, sy,  o);
    }
    if ((tid & 31) == 0) { rs[tid >> 5] = sum; rx[tid >> 5] = sx; ry[tid >> 5] = sy; }
    __syncthreads();
    if (tid == 0) {
        float S = 0.f, X = 0.f, Y = 0.f;
#pragma unroll
        for (int i = 0; i < 8; i++) { S += rs[i]; X += rx[i]; Y += ry[i]; }
        float gx_ = X / S, gy_ = Y / S;
        float mxp = (gx_ + 1.f) * 31.5f;
        float myp = (gy_ + 1.f) * 31.5f;
        out[(size_t)b * 8192 + (size_t)ty * 64 + tx]        = mxp - (float)tx;
        out[(size_t)b * 8192 + 4096 + (size_t)ty * 64 + tx] = myp - (float)ty;
    }
}

// ---------------- launch ----------------
extern "C" void kernel_launch(void* const* d_in, const int* in_sizes, int n_in,
                              void* d_out, int out_size) {
    const float* src  = (const float*)d_in[0];
    const float* tgt  = (const float*)d_in[1];
    const float* W    = (const float*)d_in[2];
    const float* bias = (const float*)d_in[3];
    float* out = (float*)d_out;

    k_norm1<<<dim3(8, 32), 256>>>(src, tgt);
    k_ctx  <<<dim3(8, 32), 256>>>(src, tgt);
    k_conv <<<dim3(8, 16, 8), 256>>>(W, bias, src, tgt);
    k_norm2<<<dim3(8, 32), 256>>>();
    k_corr <<<dim3(8, 8, 4), 256>>>();
    k_smax <<<dim3(4, 128), 256>>>();
    k_tmax <<<dim3(4, 4), 256>>>();
    k_filt <<<dim3(32, 32, 4), 256>>>();
    k_flow <<<dim3(64, 64, 4), 256>>>(out);
}

// round 3
// speedup vs baseline: 2.3338x; 2.3338x over previous
#include <cuda_runtime.h>
#include <cuda_fp16.h>
#include <math.h>
#include <stdint.h>

// ---------------- problem constants ----------------
#define IMGS 8
#define CIN  1024
#define P    1024
#define KC   28
#define KTOT 1052
#define KPAD 1056          // 33 K-stages of 32
#define COUT 2048
#define NB   4

// smem geometry for GEMM: 4 matrices (Ah,Al,Bh,Bl) x 128 rows x 40 halves (32+8 pad)
#define SROW  80           // bytes per smem row
#define MATB  10240        // bytes per matrix (128*80)
#define BUFB  40960        // bytes per stage buffer
#define SMEMB 81920        // double buffered

// ---------------- scratch ----------------
__device__ float  g_inv1[IMGS * P];
__device__ float  g_ctx [IMGS * KC * P];
__device__ __half g_Wh[COUT * KPAD], g_Wl[COUT * KPAD];
__device__ __half g_Xh[IMGS * P * KPAD], g_Xl[IMGS * P * KPAD];
__device__ float  g_St[(size_t)IMGS * P * COUT];           // conv out, [img][p][o]
__device__ __half g_Sh[(size_t)IMGS * P * COUT], g_Sl[(size_t)IMGS * P * COUT];
__device__ float  g_inv2[IMGS * P];
__device__ float  g_corr[(size_t)NB * P * P];              // [b][t][s]
__device__ float  g_smax[NB * P], g_tmax[NB * P];

__device__ const int c_dy[28] = {-3,-2,-1,0,1,2,3, -3,-2,-1,0,1,2,3, -3,-2,-1,0,1,2,3, 0,0,0,0,0,0,0};
__device__ const int c_dx[28] = {-3,-2,-1,0,1,2,3,  0, 0, 0,0,0,0,0,  3, 2, 1,0,-1,-2,-3, -3,-2,-1,0,1,2,3};

__device__ __forceinline__ const float* img_ptr(const float* src, const float* tgt, int img) {
    return (img < 4) ? (src + (size_t)img * CIN * P) : (tgt + (size_t)(img - 4) * CIN * P);
}

__device__ __forceinline__ uint32_t smem_u32(const void* p) {
    uint32_t a;
    asm("{ .reg .u64 t; cvta.to.shared.u64 t, %1; cvt.u32.u64 %0, t; }" : "=r"(a) : "l"(p));
    return a;
}
__device__ __forceinline__ void ldsm4(uint32_t r[4], uint32_t a) {
    asm volatile("ldmatrix.sync.aligned.m8n8.x4.shared.b16 {%0,%1,%2,%3}, [%4];"
        : "=r"(r[0]), "=r"(r[1]), "=r"(r[2]), "=r"(r[3]) : "r"(a));
}
__device__ __forceinline__ void mma16816(float c[4], const uint32_t a[4], const uint32_t b[2]) {
    asm volatile("mma.sync.aligned.m16n8k16.row.col.f32.f16.f16.f32 "
        "{%0,%1,%2,%3},{%4,%5,%6,%7},{%8,%9},{%0,%1,%2,%3};"
        : "+f"(c[0]), "+f"(c[1]), "+f"(c[2]), "+f"(c[3])
        : "r"(a[0]), "r"(a[1]), "r"(a[2]), "r"(a[3]), "r"(b[0]), "r"(b[1]));
}

// ---------------- GEMM mainloop (128x128 CTA tile, fp16 3-split, f32 accum) ----------------
struct Stage { uint4 a0, a1, al0, al1, b0, b1, bl0, bl1; };

__device__ __forceinline__ void ldg_stage(Stage& s,
    const __half* Ah, const __half* Al, const __half* Bh, const __half* Bl,
    int lda, int ldb, int k0, int lr, int lc)
{
    s.a0  = *(const uint4*)(Ah + (size_t)lr * lda + k0 + lc);
    s.a1  = *(const uint4*)(Ah + (size_t)(lr + 64) * lda + k0 + lc);
    s.al0 = *(const uint4*)(Al + (size_t)lr * lda + k0 + lc);
    s.al1 = *(const uint4*)(Al + (size_t)(lr + 64) * lda + k0 + lc);
    s.b0  = *(const uint4*)(Bh + (size_t)lr * ldb + k0 + lc);
    s.b1  = *(const uint4*)(Bh + (size_t)(lr + 64) * ldb + k0 + lc);
    s.bl0 = *(const uint4*)(Bl + (size_t)lr * ldb + k0 + lc);
    s.bl1 = *(const uint4*)(Bl + (size_t)(lr + 64) * ldb + k0 + lc);
}
__device__ __forceinline__ void sts_stage(const Stage& s, char* smc, uint32_t so0, uint32_t so1) {
    *(uint4*)(smc + 0 * MATB + so0) = s.a0;  *(uint4*)(smc + 0 * MATB + so1) = s.a1;
    *(uint4*)(smc + 1 * MATB + so0) = s.al0; *(uint4*)(smc + 1 * MATB + so1) = s.al1;
    *(uint4*)(smc + 2 * MATB + so0) = s.b0;  *(uint4*)(smc + 2 * MATB + so1) = s.b1;
    *(uint4*)(smc + 3 * MATB + so0) = s.bl0; *(uint4*)(smc + 3 * MATB + so1) = s.bl1;
}

__device__ __forceinline__ void compute_stage(uint32_t smb, const uint32_t aoff[2],
                                              const uint32_t boff[4], float acc[2][8][4])
{
#pragma unroll
    for (int kk = 0; kk < 2; kk++) {
        uint32_t a_h[2][4], a_l[2][4];
#pragma unroll
        for (int i = 0; i < 2; i++) {
            ldsm4(a_h[i], smb + 0 * MATB + aoff[i] + kk * 32);
            ldsm4(a_l[i], smb + 1 * MATB + aoff[i] + kk * 32);
        }
#pragma unroll
        for (int jj = 0; jj < 4; jj++) {
            uint32_t bh4[4], bl4[4];
            ldsm4(bh4, smb + 2 * MATB + boff[jj] + kk * 32);
            ldsm4(bl4, smb + 3 * MATB + boff[jj] + kk * 32);
#pragma unroll
            for (int i = 0; i < 2; i++) {
                mma16816(acc[i][jj * 2],     a_h[i], bh4 + 0);
                mma16816(acc[i][jj * 2],     a_h[i], bl4 + 0);
                mma16816(acc[i][jj * 2],     a_l[i], bh4 + 0);
                mma16816(acc[i][jj * 2 + 1], a_h[i], bh4 + 2);
                mma16816(acc[i][jj * 2 + 1], a_h[i], bl4 + 2);
                mma16816(acc[i][jj * 2 + 1], a_l[i], bh4 + 2);
            }
        }
    }
}

__device__ __forceinline__ void gemm_ml(char* smc, uint32_t smb,
    const __half* Ah, const __half* Al, const __half* Bh, const __half* Bl,
    int lda, int ldb, int K, float acc[2][8][4])
{
    int tid = threadIdx.x, lane = tid & 31, wid = tid >> 5;
    int wm = wid & 3, wn = wid >> 2;
    int lr = tid >> 2, lc = (tid & 3) * 8;
    uint32_t so0 = lr * SROW + lc * 2;
    uint32_t so1 = (lr + 64) * SROW + lc * 2;
    uint32_t aoff[2], boff[4];
#pragma unroll
    for (int i = 0; i < 2; i++)
        aoff[i] = (wm * 32 + i * 16 + (lane & 15)) * SROW + ((lane >> 4) * 8) * 2;
#pragma unroll
    for (int jj = 0; jj < 4; jj++)
        boff[jj] = (wn * 64 + jj * 16 + (lane & 7) + ((lane >> 4) & 1) * 8) * SROW
                 + (((lane >> 3) & 1) * 8) * 2;

    Stage st;
    ldg_stage(st, Ah, Al, Bh, Bl, lda, ldb, 0, lr, lc);
    sts_stage(st, smc, so0, so1);
    __syncthreads();
    int nst = K / 32;
    for (int s = 0; s < nst; s++) {
        bool nx = (s + 1) < nst;
        if (nx) ldg_stage(st, Ah, Al, Bh, Bl, lda, ldb, (s + 1) * 32, lr, lc);
        compute_stage(smb + (uint32_t)(s & 1) * BUFB, aoff, boff, acc);
        if (nx) sts_stage(st, smc + ((s + 1) & 1) * BUFB, so0, so1);
        __syncthreads();
    }
}

// ---------------- kernel 1: feature norms ----------------
__global__ void k_norm1(const float* __restrict__ src, const float* __restrict__ tgt) {
    int img = blockIdx.x, y = blockIdx.y;
    const float* f = img_ptr(src, tgt, img);
    int x = threadIdx.x & 31, cg = threadIdx.x >> 5;
    int p = y * 32 + x;
    float ss = 0.f;
    for (int c = cg; c < CIN; c += 8) { float v = f[c * P + p]; ss = fmaf(v, v, ss); }
    __shared__ float sm[8][32];
    sm[cg][x] = ss;
    __syncthreads();
    if (cg == 0) {
        float s = 0.f;
#pragma unroll
        for (int i = 0; i < 8; i++) s += sm[i][x];
        g_inv1[img * P + p] = 1.f / fmaxf(sqrtf(s), 1e-12f);
    }
}

// ---------------- kernel 2: context channels ----------------
__global__ void k_ctx(const float* __restrict__ src, const float* __restrict__ tgt) {
    int img = blockIdx.x, y = blockIdx.y;
    const float* f = img_ptr(src, tgt, img);
    int lane = threadIdx.x & 31, w = threadIdx.x >> 5;
    __shared__ float tile[8][7][32];
    __shared__ float red[28][8][32];
    float acc[28];
#pragma unroll
    for (int k = 0; k < 28; k++) acc[k] = 0.f;
    for (int c = w; c < CIN; c += 8) {
#pragma unroll
        for (int dy = 0; dy < 7; dy++) {
            int yy = y + dy - 3;
            tile[w][dy][lane] = (yy >= 0 && yy < 32) ? f[c * P + yy * 32 + lane] : 0.f;
        }
        __syncwarp();
        float v0 = tile[w][3][lane];
#pragma unroll
        for (int k = 0; k < 28; k++) {
            int xx = lane + c_dx[k];
            float v = (xx >= 0 && xx < 32) ? tile[w][c_dy[k] + 3][xx] : 0.f;
            acc[k] = fmaf(v0, v, acc[k]);
        }
        __syncwarp();
    }
#pragma unroll
    for (int k = 0; k < 28; k++) red[k][w][lane] = acc[k];
    __syncthreads();
    const float* inv = g_inv1 + img * P;
    for (int idx = threadIdx.x; idx < 28 * 32; idx += 256) {
        int k = idx >> 5, x = idx & 31;
        float s = 0.f;
#pragma unroll
        for (int i = 0; i < 8; i++) s += red[k][i][x];
        int yy = y + c_dy[k], xx = x + c_dx[k];
        float o = 0.f;
        if (yy >= 0 && yy < 32 && xx >= 0 && xx < 32)
            o = s * inv[y * 32 + x] * inv[yy * 32 + xx];
        g_ctx[((size_t)img * KC + k) * P + y * 32 + x] = o;
    }
}

// ---------------- prep: pad + split W, transpose + split inputs ----------------
__global__ void k_padW(const float* __restrict__ W) {
    int idx = blockIdx.x * 256 + threadIdx.x;
    if (idx >= COUT * KPAD) return;
    int o = idx / KPAD, k = idx - o * KPAD;
    float v = (k < KTOT) ? W[(size_t)o * KTOT + k] : 0.f;
    __half h = __float2half_rn(v);
    g_Wh[idx] = h;
    g_Wl[idx] = __float2half_rn(v - __half2float(h));
}

__global__ void k_xt(const float* __restrict__ src, const float* __restrict__ tgt) {
    int cblk = blockIdx.x, pblk = blockIdx.y, img = blockIdx.z;
    const float* f = img_ptr(src, tgt, img);
    __shared__ float tile[32][33];
    int tx = threadIdx.x;
    for (int r = threadIdx.y; r < 32; r += 8) {
        int c = cblk * 32 + r, p = pblk * 32 + tx;
        float v = 0.f;
        if (c < CIN) v = f[(size_t)c * P + p];
        else if (c < KTOT) v = g_ctx[((size_t)img * KC + (c - CIN)) * P + p];
        tile[r][tx] = v;
    }
    __syncthreads();
    for (int r = threadIdx.y; r < 32; r += 8) {
        int p = pblk * 32 + r, c = cblk * 32 + tx;
        float v = tile[tx][r];
        __half h = __float2half_rn(v);
        size_t idx = ((size_t)img * P + p) * KPAD + c;
        g_Xh[idx] = h;
        g_Xl[idx] = __float2half_rn(v - __half2float(h));
    }
}

// ---------------- conv GEMM: C[p][o] = Xt[p][:] . W[o][:] + bias, relu ----------------
__global__ void __launch_bounds__(256, 1) k_conv(const float* __restrict__ bias) {
    extern __shared__ char smc[];
    uint32_t smb = smem_u32(smc);
    int img = blockIdx.z, bm = blockIdx.y * 128, bn = blockIdx.x * 128;  // bm: p, bn: o
    const __half* Ah = g_Xh + ((size_t)img * P + bm) * KPAD;
    const __half* Al = g_Xl + ((size_t)img * P + bm) * KPAD;
    const __half* Bh = g_Wh + (size_t)bn * KPAD;
    const __half* Bl = g_Wl + (size_t)bn * KPAD;
    float acc[2][8][4] = {};
    gemm_ml(smc, smb, Ah, Al, Bh, Bl, KPAD, KPAD, KPAD, acc);

    int lane = threadIdx.x & 31, wid = threadIdx.x >> 5, wm = wid & 3, wn = wid >> 2;
    float* Sp = g_St + (size_t)img * P * COUT;
#pragma unroll
    for (int i = 0; i < 2; i++) {
        int p0 = bm + wm * 32 + i * 16 + (lane >> 2);
#pragma unroll
        for (int j = 0; j < 8; j++) {
            int o = bn + wn * 64 + j * 8 + 2 * (lane & 3);
            float2 bb = *(const float2*)(bias + o);
            float2 v0, v1;
            v0.x = fmaxf(acc[i][j][0] + bb.x, 0.f);
            v0.y = fmaxf(acc[i][j][1] + bb.y, 0.f);
            v1.x = fmaxf(acc[i][j][2] + bb.x, 0.f);
            v1.y = fmaxf(acc[i][j][3] + bb.y, 0.f);
            *(float2*)(Sp + (size_t)p0 * COUT + o) = v0;
            *(float2*)(Sp + (size_t)(p0 + 8) * COUT + o) = v1;
        }
    }
}

// ---------------- l2norm + fp16 split of conv output ----------------
__global__ void k_norm2split() {
    int row = blockIdx.x * 8 + (threadIdx.x >> 5);   // img*P + p
    int lane = threadIdx.x & 31;
    const float4* p4 = (const float4*)(g_St + (size_t)row * COUT);
    __half* sh = g_Sh + (size_t)row * COUT;
    __half* sl = g_Sl + (size_t)row * COUT;
    float ss = 0.f;
    for (int i = lane; i < COUT / 4; i += 32) {
        float4 v = p4[i];
        ss = fmaf(v.x, v.x, fmaf(v.y, v.y, fmaf(v.z, v.z, fmaf(v.w, v.w, ss))));
        __half h0 = __float2half_rn(v.x), h1 = __float2half_rn(v.y);
        __half h2 = __float2half_rn(v.z), h3 = __float2half_rn(v.w);
        __half l0 = __float2half_rn(v.x - __half2float(h0));
        __half l1 = __float2half_rn(v.y - __half2float(h1));
        __half l2 = __float2half_rn(v.z - __half2float(h2));
        __half l3 = __float2half_rn(v.w - __half2float(h3));
        *(__half2*)(sh + i * 4)     = __halves2half2(h0, h1);
        *(__half2*)(sh + i * 4 + 2) = __halves2half2(h2, h3);
        *(__half2*)(sl + i * 4)     = __halves2half2(l0, l1);
        *(__half2*)(sl + i * 4 + 2) = __halves2half2(l2, l3);
    }
#pragma unroll
    for (int o = 16; o > 0; o >>= 1) ss += __shfl_xor_sync(0xffffffffu, ss, o);
    if (lane == 0) g_inv2[row] = rsqrtf(ss + 1e-6f);
}

// ---------------- corr GEMM: C[s][t] scaled, stored as [t][s] ----------------
__global__ void __launch_bounds__(256, 1) k_corr() {
    extern __shared__ char smc[];
    uint32_t smb = smem_u32(smc);
    int b = blockIdx.z, bm = blockIdx.y * 128, bn = blockIdx.x * 128;  // bm: s, bn: t
    const __half* Ah = g_Sh + ((size_t)b * P + bm) * COUT;
    const __half* Al = g_Sl + ((size_t)b * P + bm) * COUT;
    const __half* Bh = g_Sh + ((size_t)(4 + b) * P + bn) * COUT;
    const __half* Bl = g_Sl + ((size_t)(4 + b) * P + bn) * COUT;
    float acc[2][8][4] = {};
    gemm_ml(smc, smb, Ah, Al, Bh, Bl, COUT, COUT, COUT, acc);

    int lane = threadIdx.x & 31, wid = threadIdx.x >> 5, wm = wid & 3, wn = wid >> 2;
    const float* invs = g_inv2 + b * P;
    const float* invt = g_inv2 + (4 + b) * P;
    float* C = g_corr + (size_t)b * P * P;
#pragma unroll
    for (int i = 0; i < 2; i++) {
        int s0 = bm + wm * 32 + i * 16 + (lane >> 2);
        float is0 = invs[s0], is1 = invs[s0 + 8];
#pragma unroll
        for (int j = 0; j < 8; j++) {
            int t0 = bn + wn * 64 + j * 8 + 2 * (lane & 3);
            float it0 = invt[t0], it1 = invt[t0 + 1];
            C[(size_t)t0 * P + s0]           = acc[i][j][0] * is0 * it0;
            C[(size_t)(t0 + 1) * P + s0]     = acc[i][j][1] * is0 * it1;
            C[(size_t)t0 * P + s0 + 8]       = acc[i][j][2] * is1 * it0;
            C[(size_t)(t0 + 1) * P + s0 + 8] = acc[i][j][3] * is1 * it1;
        }
    }
}

// ---------------- maxes + mutual-NN filter (corr is [b][t][s]) ----------------
__global__ void k_smax() {   // smax[s] = max over t
    int b = blockIdx.x;
    int s = blockIdx.y * 256 + threadIdx.x;
    const float* c = g_corr + (size_t)b * P * P;
    float m = -INFINITY;
    for (int t = 0; t < P; t++) m = fmaxf(m, c[(size_t)t * P + s]);
    g_smax[b * P + s] = m;
}
__global__ void k_tmax() {   // tmax[t] = max over s
    int b = blockIdx.x;
    int t = blockIdx.y * 8 + (threadIdx.x >> 5);
    int lane = threadIdx.x & 31;
    const float* row = g_corr + ((size_t)b * P + t) * P;
    float m = -INFINITY;
    for (int s = lane; s < P; s += 32) m = fmaxf(m, row[s]);
#pragma unroll
    for (int o = 16; o > 0; o >>= 1) m = fmaxf(m, __shfl_xor_sync(0xffffffffu, m, o));
    if (lane == 0) g_tmax[b * P + t] = m;
}
__global__ void k_filt() {
    int b = blockIdx.y;
    int e = blockIdx.x * 256 + threadIdx.x;
    int t = e >> 10, s = e & 1023;
    float* c = g_corr + (size_t)b * P * P;
    float v = c[e];
    float sm = g_smax[b * P + s]; sm = (sm == 0.f) ? 1e-30f : sm;
    float tm = g_tmax[b * P + t]; tm = (tm == 0.f) ? 1e-30f : tm;
    c[e] = v * (v / sm) * (v / tm);
}

// ---------------- fused resize + softmax + soft-argmax + flow ----------------
__global__ void __launch_bounds__(256) k_flow(float* __restrict__ out) {
    int tx = blockIdx.x, ty = blockIdx.y, b = blockIdx.z;
    int tid = threadIdx.x;
    const float sc = 31.f / 63.f;
    float fy = ty * sc; int y0 = (int)fy; int y1 = min(y0 + 1, 31); float wy = fy - (float)y0;
    float fx = tx * sc; int x0 = (int)fx; int x1 = min(x0 + 1, 31); float wx = fx - (float)x0;
    const float* C = g_corr + (size_t)b * P * P;
    const float* r00 = C + (size_t)(y0 * 32 + x0) * P;
    const float* r01 = C + (size_t)(y0 * 32 + x1) * P;
    const float* r10 = C + (size_t)(y1 * 32 + x0) * P;
    const float* r11 = C + (size_t)(y1 * 32 + x1) * P;
    float w00 = (1.f - wy) * (1.f - wx), w01 = (1.f - wy) * wx;
    float w10 = wy * (1.f - wx),         w11 = wy * wx;
    __shared__ float m[P];
    for (int s = tid; s < P; s += 256)
        m[s] = w00 * r00[s] + w01 * r01[s] + w10 * r10[s] + w11 * r11[s];
    __syncthreads();
    float mx = -INFINITY;
    for (int s = tid; s < P; s += 256) mx = fmaxf(mx, m[s]);
    __shared__ float rd[8];
#pragma unroll
    for (int o = 16; o > 0; o >>= 1) mx = fmaxf(mx, __shfl_xor_sync(0xffffffffu, mx, o));
    if ((tid & 31) == 0) rd[tid >> 5] = mx;
    __syncthreads();
    float M = -INFINITY;
#pragma unroll
    for (int i = 0; i < 8; i++) M = fmaxf(M, rd[i]);
    float sum = 0.f, sx = 0.f, sy = 0.f;
    for (int s = tid; s < 4096; s += 256) {
        int i = s >> 6, j = s & 63;
        float gy = i * sc; int yy0 = (int)gy; int yy1 = min(yy0 + 1, 31); float a = gy - (float)yy0;
        float gx = j * sc; int xx0 = (int)gx; int xx1 = min(xx0 + 1, 31); float bq = gx - (float)xx0;
        float v = (1.f - a) * ((1.f - bq) * m[yy0 * 32 + xx0] + bq * m[yy0 * 32 + xx1])
                +        a  * ((1.f - bq) * m[yy1 * 32 + xx0] + bq * m[yy1 * 32 + xx1]);
        float e = expf((v - M) * 50.f);
        sum += e;
        sx = fmaf(e, -1.f + j * (2.f / 63.f), sx);
        sy = fmaf(e, -1.f + i * (2.f / 63.f), sy);
    }
    __shared__ float rs[8], rx[8], ry[8];
#pragma unroll
    for (int o = 16; o > 0; o >>= 1) {
        sum += __shfl_xor_sync(0xffffffffu, sum, o);
        sx  += __shfl_xor_sync(0xffffffffu, sx,  o);
        sy  += __shfl_xor_sync(0xffffffffu, sy,  o);
    }
    if ((tid & 31) == 0) { rs[tid >> 5] = sum; rx[tid >> 5] = sx; ry[tid >> 5] = sy; }
    __syncthreads();
    if (tid == 0) {
        float S = 0.f, X = 0.f, Y = 0.f;
#pragma unroll
        for (int i = 0; i < 8; i++) { S += rs[i]; X += rx[i]; Y += ry[i]; }
        float gx_ = X / S, gy_ = Y / S;
        out[(size_t)b * 8192 + (size_t)ty * 64 + tx]        = (gx_ + 1.f) * 31.5f - (float)tx;
        out[(size_t)b * 8192 + 4096 + (size_t)ty * 64 + tx] = (gy_ + 1.f) * 31.5f - (float)ty;
    }
}

// ---------------- launch ----------------
extern "C" void kernel_launch(void* const* d_in, const int* in_sizes, int n_in,
                              void* d_out, int out_size) {
    const float* src  = (const float*)d_in[0];
    const float* tgt  = (const float*)d_in[1];
    const float* W    = (const float*)d_in[2];
    const float* bias = (const float*)d_in[3];
    float* out = (float*)d_out;

    cudaFuncSetAttribute(k_conv, cudaFuncAttributeMaxDynamicSharedMemorySize, SMEMB);
    cudaFuncSetAttribute(k_corr, cudaFuncAttributeMaxDynamicSharedMemorySize, SMEMB);

    k_norm1<<<dim3(8, 32), 256>>>(src, tgt);
    k_ctx  <<<dim3(8, 32), 256>>>(src, tgt);
    k_padW <<<(COUT * KPAD + 255) / 256, 256>>>(W);
    k_xt   <<<dim3(33, 32, 8), dim3(32, 8)>>>(src, tgt);
    k_conv <<<dim3(16, 8, 8), 256, SMEMB>>>(bias);
    k_norm2split<<<1024, 256>>>();
    k_corr <<<dim3(8, 8, 4), 256, SMEMB>>>();
    k_smax <<<dim3(4, 4), 256>>>();
    k_tmax <<<dim3(4, 128), 256>>>();
    k_filt <<<dim3(4096, 4), 256>>>();
    k_flow <<<dim3(64, 64, 4), 256>>>(out);
}

// round 4
// speedup vs baseline: 2.3656x; 1.0136x over previous
#include <cuda_runtime.h>
#include <cuda_fp16.h>
#include <math.h>
#include <stdint.h>

// ---------------- problem constants ----------------
#define IMGS 8
#define CIN  1024
#define P    1024
#define KC   28
#define KTOT 1052
#define KPAD 1056          // 33 K-stages of 32
#define COUT 2048
#define NB   4

// smem geometry: 4 matrices (Ah,Al,Bh,Bl) x 128 rows x 40 halves (32+8 pad)
#define SROW  80
#define MATB  10240
#define BUFB  40960
#define SMEMB 81920        // double buffered

// ---------------- scratch ----------------
__device__ float  g_inv1[IMGS * P];
__device__ float  g_ctx [IMGS * KC * P];
__device__ __align__(16) __half g_Wh[COUT * KPAD], g_Wl[COUT * KPAD];
__device__ __align__(16) __half g_Xh[IMGS * P * KPAD], g_Xl[IMGS * P * KPAD];
__device__ __align__(16) __half g_Sh[(size_t)IMGS * P * COUT], g_Sl[(size_t)IMGS * P * COUT];
__device__ float  g_ssum[IMGS * P];
__device__ float  g_inv2[IMGS * P];
__device__ float  g_corr[(size_t)NB * P * P];              // raw corr, [b][t][s]
__device__ float  g_isx[NB * P], g_itx[NB * P];            // 1/guarded max

__device__ const int c_dy[28] = {-3,-2,-1,0,1,2,3, -3,-2,-1,0,1,2,3, -3,-2,-1,0,1,2,3, 0,0,0,0,0,0,0};
__device__ const int c_dx[28] = {-3,-2,-1,0,1,2,3,  0, 0, 0,0,0,0,0,  3, 2, 1,0,-1,-2,-3, -3,-2,-1,0,1,2,3};

__device__ __forceinline__ const float* img_ptr(const float* src, const float* tgt, int img) {
    return (img < 4) ? (src + (size_t)img * CIN * P) : (tgt + (size_t)(img - 4) * CIN * P);
}
__device__ __forceinline__ uint32_t smem_u32(const void* p) {
    uint32_t a;
    asm("{ .reg .u64 t; cvta.to.shared.u64 t, %1; cvt.u32.u64 %0, t; }" : "=r"(a) : "l"(p));
    return a;
}
__device__ __forceinline__ void cp16(uint32_t dst, const void* src) {
    asm volatile("cp.async.cg.shared.global [%0], [%1], 16;" :: "r"(dst), "l"(src) : "memory");
}
__device__ __forceinline__ void ldsm4(uint32_t r[4], uint32_t a) {
    asm volatile("ldmatrix.sync.aligned.m8n8.x4.shared.b16 {%0,%1,%2,%3}, [%4];"
        : "=r"(r[0]), "=r"(r[1]), "=r"(r[2]), "=r"(r[3]) : "r"(a));
}
__device__ __forceinline__ void mma16816(float c[4], const uint32_t a[4], const uint32_t b[2]) {
    asm volatile("mma.sync.aligned.m16n8k16.row.col.f32.f16.f16.f32 "
        "{%0,%1,%2,%3},{%4,%5,%6,%7},{%8,%9},{%0,%1,%2,%3};"
        : "+f"(c[0]), "+f"(c[1]), "+f"(c[2]), "+f"(c[3])
        : "r"(a[0]), "r"(a[1]), "r"(a[2]), "r"(a[3]), "r"(b[0]), "r"(b[1]));
}

// ---------------- GEMM compute for one 128x128x32 stage ----------------
__device__ __forceinline__ void compute_stage(uint32_t smb, const uint32_t aoff[2],
                                              const uint32_t boff[4], float acc[2][8][4])
{
#pragma unroll
    for (int kk = 0; kk < 2; kk++) {
        uint32_t a_h[2][4], a_l[2][4];
#pragma unroll
        for (int i = 0; i < 2; i++) {
            ldsm4(a_h[i], smb + 0 * MATB + aoff[i] + kk * 32);
            ldsm4(a_l[i], smb + 1 * MATB + aoff[i] + kk * 32);
        }
#pragma unroll
        for (int jj = 0; jj < 4; jj++) {
            uint32_t bh4[4], bl4[4];
            ldsm4(bh4, smb + 2 * MATB + boff[jj] + kk * 32);
            ldsm4(bl4, smb + 3 * MATB + boff[jj] + kk * 32);
#pragma unroll
            for (int i = 0; i < 2; i++) {
                mma16816(acc[i][jj * 2],     a_h[i], bh4 + 0);
                mma16816(acc[i][jj * 2],     a_h[i], bl4 + 0);
                mma16816(acc[i][jj * 2],     a_l[i], bh4 + 0);
                mma16816(acc[i][jj * 2 + 1], a_h[i], bh4 + 2);
                mma16816(acc[i][jj * 2 + 1], a_h[i], bl4 + 2);
                mma16816(acc[i][jj * 2 + 1], a_l[i], bh4 + 2);
            }
        }
    }
}

// ---------------- GEMM mainloop: cp.async double-buffered ----------------
__device__ __forceinline__ void gemm_ml(uint32_t smb,
    const __half* Ah, const __half* Al, const __half* Bh, const __half* Bl,
    int lda, int ldb, int K, float acc[2][8][4])
{
    int tid = threadIdx.x, lane = tid & 31, wid = tid >> 5;
    int wm = wid & 3, wn = wid >> 2;
    int lr = tid >> 2, lc = (tid & 3) * 8;
    uint32_t ro0 = (uint32_t)lr * SROW + lc * 2;
    uint32_t ro1 = (uint32_t)(lr + 64) * SROW + lc * 2;
    const __half* pA0  = Ah + (size_t)lr * lda + lc;
    const __half* pA1  = Ah + (size_t)(lr + 64) * lda + lc;
    const __half* pAl0 = Al + (size_t)lr * lda + lc;
    const __half* pAl1 = Al + (size_t)(lr + 64) * lda + lc;
    const __half* pB0  = Bh + (size_t)lr * ldb + lc;
    const __half* pB1  = Bh + (size_t)(lr + 64) * ldb + lc;
    const __half* pBl0 = Bl + (size_t)lr * ldb + lc;
    const __half* pBl1 = Bl + (size_t)(lr + 64) * ldb + lc;

    uint32_t aoff[2], boff[4];
#pragma unroll
    for (int i = 0; i < 2; i++)
        aoff[i] = (wm * 32 + i * 16 + (lane & 15)) * SROW + ((lane >> 4) * 8) * 2;
#pragma unroll
    for (int jj = 0; jj < 4; jj++)
        boff[jj] = (wn * 64 + jj * 16 + (lane & 7) + ((lane >> 4) & 1) * 8) * SROW
                 + (((lane >> 3) & 1) * 8) * 2;

#define ISSUE(s, k0) do { \
        uint32_t bb = smb + (uint32_t)((s) & 1) * BUFB; \
        cp16(bb + 0 * MATB + ro0, pA0 + (k0));  cp16(bb + 0 * MATB + ro1, pA1 + (k0)); \
        cp16(bb + 1 * MATB + ro0, pAl0 + (k0)); cp16(bb + 1 * MATB + ro1, pAl1 + (k0)); \
        cp16(bb + 2 * MATB + ro0, pB0 + (k0));  cp16(bb + 2 * MATB + ro1, pB1 + (k0)); \
        cp16(bb + 3 * MATB + ro0, pBl0 + (k0)); cp16(bb + 3 * MATB + ro1, pBl1 + (k0)); \
        asm volatile("cp.async.commit_group;" ::: "memory"); \
    } while (0)

    int nst = K / 32;
    ISSUE(0, 0);
    for (int s = 0; s < nst; s++) {
        if (s + 1 < nst) {
            ISSUE(s + 1, (s + 1) * 32);
            asm volatile("cp.async.wait_group 1;" ::: "memory");
        } else {
            asm volatile("cp.async.wait_group 0;" ::: "memory");
        }
        __syncthreads();
        compute_stage(smb + (uint32_t)(s & 1) * BUFB, aoff, boff, acc);
        __syncthreads();
    }
#undef ISSUE
}

// ---------------- kernel 1: feature norms ----------------
__global__ void k_norm1(const float* __restrict__ src, const float* __restrict__ tgt) {
    int img = blockIdx.x, y = blockIdx.y;
    const float* f = img_ptr(src, tgt, img);
    int x = threadIdx.x & 31, cg = threadIdx.x >> 5;
    int p = y * 32 + x;
    float ss = 0.f;
    for (int c = cg; c < CIN; c += 8) { float v = f[c * P + p]; ss = fmaf(v, v, ss); }
    __shared__ float sm[8][32];
    sm[cg][x] = ss;
    __syncthreads();
    if (cg == 0) {
        float s = 0.f;
#pragma unroll
        for (int i = 0; i < 8; i++) s += sm[i][x];
        g_inv1[img * P + p] = 1.f / fmaxf(sqrtf(s), 1e-12f);
    }
}

// ---------------- kernel 2: context channels ----------------
__global__ void k_ctx(const float* __restrict__ src, const float* __restrict__ tgt) {
    int img = blockIdx.x, y = blockIdx.y;
    const float* f = img_ptr(src, tgt, img);
    int lane = threadIdx.x & 31, w = threadIdx.x >> 5;
    __shared__ float tile[8][7][32];
    __shared__ float red[28][8][32];
    float acc[28];
#pragma unroll
    for (int k = 0; k < 28; k++) acc[k] = 0.f;
    for (int c = w; c < CIN; c += 8) {
#pragma unroll
        for (int dy = 0; dy < 7; dy++) {
            int yy = y + dy - 3;
            tile[w][dy][lane] = (yy >= 0 && yy < 32) ? f[c * P + yy * 32 + lane] : 0.f;
        }
        __syncwarp();
        float v0 = tile[w][3][lane];
#pragma unroll
        for (int k = 0; k < 28; k++) {
            int xx = lane + c_dx[k];
            float v = (xx >= 0 && xx < 32) ? tile[w][c_dy[k] + 3][xx] : 0.f;
            acc[k] = fmaf(v0, v, acc[k]);
        }
        __syncwarp();
    }
#pragma unroll
    for (int k = 0; k < 28; k++) red[k][w][lane] = acc[k];
    __syncthreads();
    const float* inv = g_inv1 + img * P;
    for (int idx = threadIdx.x; idx < 28 * 32; idx += 256) {
        int k = idx >> 5, x = idx & 31;
        float s = 0.f;
#pragma unroll
        for (int i = 0; i < 8; i++) s += red[k][i][x];
        int yy = y + c_dy[k], xx = x + c_dx[k];
        float o = 0.f;
        if (yy >= 0 && yy < 32 && xx >= 0 && xx < 32)
            o = s * inv[y * 32 + x] * inv[yy * 32 + xx];
        g_ctx[((size_t)img * KC + k) * P + y * 32 + x] = o;
    }
}

// ---------------- prep: pad + split W, zero ssum, transpose + split inputs ----------------
__global__ void k_padW(const float* __restrict__ W) {
    int idx = blockIdx.x * 256 + threadIdx.x;
    if (idx < IMGS * P) g_ssum[idx] = 0.f;
    if (idx >= COUT * KPAD) return;
    int o = idx / KPAD, k = idx - o * KPAD;
    float v = (k < KTOT) ? W[(size_t)o * KTOT + k] : 0.f;
    __half h = __float2half_rn(v);
    g_Wh[idx] = h;
    g_Wl[idx] = __float2half_rn(v - __half2float(h));
}

__global__ void k_xt(const float* __restrict__ src, const float* __restrict__ tgt) {
    int cblk = blockIdx.x, pblk = blockIdx.y, img = blockIdx.z;
    const float* f = img_ptr(src, tgt, img);
    __shared__ float tile[32][33];
    int tx = threadIdx.x;
    for (int r = threadIdx.y; r < 32; r += 8) {
        int c = cblk * 32 + r, p = pblk * 32 + tx;
        float v = 0.f;
        if (c < CIN) v = f[(size_t)c * P + p];
        else if (c < KTOT) v = g_ctx[((size_t)img * KC + (c - CIN)) * P + p];
        tile[r][tx] = v;
    }
    __syncthreads();
    for (int r = threadIdx.y; r < 32; r += 8) {
        int p = pblk * 32 + r, c = cblk * 32 + tx;
        float v = tile[tx][r];
        __half h = __float2half_rn(v);
        size_t idx = ((size_t)img * P + p) * KPAD + c;
        g_Xh[idx] = h;
        g_Xl[idx] = __float2half_rn(v - __half2float(h));
    }
}

// ---------------- conv GEMM: writes Sh/Sl + sum-of-squares atomics ----------------
__global__ void __launch_bounds__(256, 2) k_conv(const float* __restrict__ bias) {
    extern __shared__ char smc[];
    __shared__ float sss[128];
    uint32_t smb = smem_u32(smc);
    int img = blockIdx.z, bm = blockIdx.y * 128, bn = blockIdx.x * 128;  // bm: p, bn: o
    const __half* Ah = g_Xh + ((size_t)img * P + bm) * KPAD;
    const __half* Al = g_Xl + ((size_t)img * P + bm) * KPAD;
    const __half* Bh = g_Wh + (size_t)bn * KPAD;
    const __half* Bl = g_Wl + (size_t)bn * KPAD;
    float acc[2][8][4] = {};
    gemm_ml(smb, Ah, Al, Bh, Bl, KPAD, KPAD, KPAD, acc);

    if (threadIdx.x < 128) sss[threadIdx.x] = 0.f;
    __syncthreads();

    int lane = threadIdx.x & 31, wid = threadIdx.x >> 5, wm = wid & 3, wn = wid >> 2;
    __half* Shp = g_Sh + (size_t)img * P * COUT;
    __half* Slp = g_Sl + (size_t)img * P * COUT;
#pragma unroll
    for (int i = 0; i < 2; i++) {
        int pl0 = wm * 32 + i * 16 + (lane >> 2);
        int p0 = bm + pl0;
        float q0 = 0.f, q1 = 0.f;
#pragma unroll
        for (int j = 0; j < 8; j++) {
            int o = bn + wn * 64 + j * 8 + 2 * (lane & 3);
            float2 bb = *(const float2*)(bias + o);
            float a0 = fmaxf(acc[i][j][0] + bb.x, 0.f);
            float a1 = fmaxf(acc[i][j][1] + bb.y, 0.f);
            float a2 = fmaxf(acc[i][j][2] + bb.x, 0.f);
            float a3 = fmaxf(acc[i][j][3] + bb.y, 0.f);
            q0 = fmaf(a0, a0, fmaf(a1, a1, q0));
            q1 = fmaf(a2, a2, fmaf(a3, a3, q1));
            __half h0 = __float2half_rn(a0), h1 = __float2half_rn(a1);
            __half h2 = __float2half_rn(a2), h3 = __float2half_rn(a3);
            *(__half2*)(Shp + (size_t)p0 * COUT + o)       = __halves2half2(h0, h1);
            *(__half2*)(Shp + (size_t)(p0 + 8) * COUT + o) = __halves2half2(h2, h3);
            *(__half2*)(Slp + (size_t)p0 * COUT + o)       =
                __halves2half2(__float2half_rn(a0 - __half2float(h0)), __float2half_rn(a1 - __half2float(h1)));
            *(__half2*)(Slp + (size_t)(p0 + 8) * COUT + o) =
                __halves2half2(__float2half_rn(a2 - __half2float(h2)), __float2half_rn(a3 - __half2float(h3)));
        }
        atomicAdd(&sss[pl0], q0);
        atomicAdd(&sss[pl0 + 8], q1);
    }
    __syncthreads();
    if (threadIdx.x < 128) atomicAdd(&g_ssum[img * P + bm + threadIdx.x], sss[threadIdx.x]);
}

__global__ void k_inv2() {
    int i = blockIdx.x * 256 + threadIdx.x;
    if (i < IMGS * P) g_inv2[i] = rsqrtf(g_ssum[i] + 1e-6f);
}

// ---------------- corr GEMM: raw corr stored [b][t][s], scaled ----------------
__global__ void __launch_bounds__(256, 2) k_corr() {
    extern __shared__ char smc[];
    uint32_t smb = smem_u32(smc);
    int b = blockIdx.z, bm = blockIdx.y * 128, bn = blockIdx.x * 128;  // bm: s, bn: t
    const __half* Ah = g_Sh + ((size_t)b * P + bm) * COUT;
    const __half* Al = g_Sl + ((size_t)b * P + bm) * COUT;
    const __half* Bh = g_Sh + ((size_t)(4 + b) * P + bn) * COUT;
    const __half* Bl = g_Sl + ((size_t)(4 + b) * P + bn) * COUT;
    float acc[2][8][4] = {};
    gemm_ml(smb, Ah, Al, Bh, Bl, COUT, COUT, COUT, acc);

    int lane = threadIdx.x & 31, wid = threadIdx.x >> 5, wm = wid & 3, wn = wid >> 2;
    const float* invs = g_inv2 + b * P;
    const float* invt = g_inv2 + (4 + b) * P;
    float* C = g_corr + (size_t)b * P * P;
#pragma unroll
    for (int i = 0; i < 2; i++) {
        int s0 = bm + wm * 32 + i * 16 + (lane >> 2);
        float is0 = invs[s0], is1 = invs[s0 + 8];
#pragma unroll
        for (int j = 0; j < 8; j++) {
            int t0 = bn + wn * 64 + j * 8 + 2 * (lane & 3);
            float it0 = invt[t0], it1 = invt[t0 + 1];
            C[(size_t)t0 * P + s0]           = acc[i][j][0] * is0 * it0;
            C[(size_t)(t0 + 1) * P + s0]     = acc[i][j][1] * is0 * it1;
            C[(size_t)t0 * P + s0 + 8]       = acc[i][j][2] * is1 * it0;
            C[(size_t)(t0 + 1) * P + s0 + 8] = acc[i][j][3] * is1 * it1;
        }
    }
}

// ---------------- reciprocal maxes (corr is [b][t][s]) ----------------
__global__ void k_smax() {   // over t for each s
    int b = blockIdx.x;
    int s = blockIdx.y * 256 + threadIdx.x;
    const float* c = g_corr + (size_t)b * P * P;
    float m = -INFINITY;
    for (int t = 0; t < P; t++) m = fmaxf(m, c[(size_t)t * P + s]);
    if (m == 0.f) m = 1e-30f;
    g_isx[b * P + s] = 1.f / m;
}
__global__ void k_tmax() {   // over s for each t
    int b = blockIdx.x;
    int t = blockIdx.y * 8 + (threadIdx.x >> 5);
    int lane = threadIdx.x & 31;
    const float* row = g_corr + ((size_t)b * P + t) * P;
    float m = -INFINITY;
    for (int s = lane; s < P; s += 32) m = fmaxf(m, row[s]);
#pragma unroll
    for (int o = 16; o > 0; o >>= 1) m = fmaxf(m, __shfl_xor_sync(0xffffffffu, m, o));
    if (lane == 0) {
        if (m == 0.f) m = 1e-30f;
        g_itx[b * P + t] = 1.f / m;
    }
}

// ---------------- fused filter + resize + softmax + soft-argmax + flow ----------------
__global__ void __launch_bounds__(256) k_flow(float* __restrict__ out) {
    int tx = blockIdx.x, ty = blockIdx.y, b = blockIdx.z;
    int tid = threadIdx.x;
    const float sc = 31.f / 63.f;
    float fy = ty * sc; int y0 = (int)fy; int y1 = min(y0 + 1, 31); float wy = fy - (float)y0;
    float fx = tx * sc; int x0 = (int)fx; int x1 = min(x0 + 1, 31); float wx = fx - (float)x0;
    int t00 = y0 * 32 + x0, t01 = y0 * 32 + x1, t10 = y1 * 32 + x0, t11 = y1 * 32 + x1;
    const float* C = g_corr + (size_t)b * P * P;
    const float* r00 = C + (size_t)t00 * P;
    const float* r01 = C + (size_t)t01 * P;
    const float* r10 = C + (size_t)t10 * P;
    const float* r11 = C + (size_t)t11 * P;
    float ww00 = (1.f - wy) * (1.f - wx) * g_itx[b * P + t00];
    float ww01 = (1.f - wy) * wx         * g_itx[b * P + t01];
    float ww10 = wy * (1.f - wx)         * g_itx[b * P + t10];
    float ww11 = wy * wx                 * g_itx[b * P + t11];
    const float* isx = g_isx + b * P;
    __shared__ float m[P];
    for (int s = tid; s < P; s += 256) {
        float v00 = r00[s], v01 = r01[s], v10 = r10[s], v11 = r11[s];
        float a = ww00 * v00 * v00 * v00 + ww01 * v01 * v01 * v01
                + ww10 * v10 * v10 * v10 + ww11 * v11 * v11 * v11;
        m[s] = a * isx[s];
    }
    __syncthreads();
    float mx = -INFINITY;
    for (int s = tid; s < P; s += 256) mx = fmaxf(mx, m[s]);
    __shared__ float rd[8];
#pragma unroll
    for (int o = 16; o > 0; o >>= 1) mx = fmaxf(mx, __shfl_xor_sync(0xffffffffu, mx, o));
    if ((tid & 31) == 0) rd[tid >> 5] = mx;
    __syncthreads();
    float M = -INFINITY;
#pragma unroll
    for (int i = 0; i < 8; i++) M = fmaxf(M, rd[i]);
    float sum = 0.f, sx = 0.f, sy = 0.f;
    for (int s = tid; s < 4096; s += 256) {
        int i = s >> 6, j = s & 63;
        float gy = i * sc; int yy0 = (int)gy; int yy1 = min(yy0 + 1, 31); float a = gy - (float)yy0;
        float gx = j * sc; int xx0 = (int)gx; int xx1 = min(xx0 + 1, 31); float bq = gx - (float)xx0;
        float v = (1.f - a) * ((1.f - bq) * m[yy0 * 32 + xx0] + bq * m[yy0 * 32 + xx1])
                +        a  * ((1.f - bq) * m[yy1 * 32 + xx0] + bq * m[yy1 * 32 + xx1]);
        float e = expf((v - M) * 50.f);
        sum += e;
        sx = fmaf(e, -1.f + j * (2.f / 63.f), sx);
        sy = fmaf(e, -1.f + i * (2.f / 63.f), sy);
    }
    __shared__ float rs[8], rx[8], ry[8];
#pragma unroll
    for (int o = 16; o > 0; o >>= 1) {
        sum += __shfl_xor_sync(0xffffffffu, sum, o);
        sx  += __shfl_xor_sync(0xffffffffu, sx,  o);
        sy  += __shfl_xor_sync(0xffffffffu, sy,  o);
    }
    if ((tid & 31) == 0) { rs[tid >> 5] = sum; rx[tid >> 5] = sx; ry[tid >> 5] = sy; }
    __syncthreads();
    if (tid == 0) {
        float S = 0.f, X = 0.f, Y = 0.f;
#pragma unroll
        for (int i = 0; i < 8; i++) { S += rs[i]; X += rx[i]; Y += ry[i]; }
        float gx_ = X / S, gy_ = Y / S;
        out[(size_t)b * 8192 + (size_t)ty * 64 + tx]        = (gx_ + 1.f) * 31.5f - (float)tx;
        out[(size_t)b * 8192 + 4096 + (size_t)ty * 64 + tx] = (gy_ + 1.f) * 31.5f - (float)ty;
    }
}

// ---------------- launch ----------------
extern "C" void kernel_launch(void* const* d_in, const int* in_sizes, int n_in,
                              void* d_out, int out_size) {
    const float* src  = (const float*)d_in[0];
    const float* tgt  = (const float*)d_in[1];
    const float* W    = (const float*)d_in[2];
    const float* bias = (const float*)d_in[3];
    float* out = (float*)d_out;

    cudaFuncSetAttribute(k_conv, cudaFuncAttributeMaxDynamicSharedMemorySize, SMEMB);
    cudaFuncSetAttribute(k_corr, cudaFuncAttributeMaxDynamicSharedMemorySize, SMEMB);

    k_norm1<<<dim3(8, 32), 256>>>(src, tgt);
    k_ctx  <<<dim3(8, 32), 256>>>(src, tgt);
    k_padW <<<(COUT * KPAD + 255) / 256, 256>>>(W);
    k_xt   <<<dim3(33, 32, 8), dim3(32, 8)>>>(src, tgt);
    k_conv <<<dim3(16, 8, 8), 256, SMEMB>>>(bias);
    k_inv2 <<<32, 256>>>();
    k_corr <<<dim3(8, 8, 4), 256, SMEMB>>>();
    k_smax <<<dim3(4, 4), 256>>>();
    k_tmax <<<dim3(4, 128), 256>>>();
    k_flow <<<dim3(64, 64, 4), 256>>>(out);
}